// round 8
// baseline (speedup 1.0000x reference)
#include <cuda_runtime.h>
#include <cstdint>

#define THREADS 256

namespace {
constexpr int H_   = 16;
constexpr int N_   = 4096;
constexpr int D_   = 128;
constexpr int CHK  = 128;
constexpr int NBLK = 32;
constexpr int BHc  = 32;
constexpr int NCTA = 1024;

constexpr int STT = 132;   // transposed-storage chunk stride [k][m]
constexpr int STK = 36;    // K-major chunk stride [m][k] (32 + pad4)
constexpr int STS_ = 132;  // scores stride

// kdv smem (floats): tab + 2x (V,K) chunk bufs [32][STT]
constexpr int KF_TAB = 0;
constexpr int KF_V0  = 128;
constexpr int KF_K0  = KF_V0 + 32 * STT;
constexpr int KF_V1  = KF_K0 + 32 * STT;
constexpr int KF_K1  = KF_V1 + 32 * STT;
constexpr int SMEM_KDV = (KF_K1 + 32 * STT) * 4;      // 68,096 B

// out smem (floats): tab + scores[64][STS_] + 2x A[64][STK] + 2x B[128][STK]
constexpr int OF_TAB = 0;
constexpr int OF_SC  = 128;
constexpr int OF_A0  = OF_SC + 64 * STS_;
constexpr int OF_A1  = OF_A0 + 64 * STK;
constexpr int OF_B0  = OF_A1 + 64 * STK;
constexpr int OF_B1  = OF_B0 + 128 * STK;             // B bufs also host v [32][STT] chunks
constexpr int SMEM_OUT = (OF_B1 + 128 * STK) * 4;     // 89,600 B
}

__device__ float g_states[(size_t)NCTA * D_ * D_];

// ---------------------------------------------------------------------------
__device__ __forceinline__ uint32_t smem_u32(const void* p) {
    uint32_t a;
    asm("{ .reg .u64 t; cvta.to.shared.u64 t, %1; cvt.u32.u64 %0, t; }" : "=r"(a) : "l"(p));
    return a;
}
__device__ __forceinline__ uint32_t f2tf(float x) {
    uint32_t u;
    asm("cvt.rna.tf32.f32 %0, %1;" : "=r"(u) : "f"(x));
    return u;
}
__device__ __forceinline__ void cpa16(uint32_t dst, const float* src) {
    asm volatile("cp.async.cg.shared.global [%0], [%1], 16;" :: "r"(dst), "l"(src));
}
#define CP_COMMIT() asm volatile("cp.async.commit_group;" ::: "memory")
template <int N> __device__ __forceinline__ void cp_wait() {
    asm volatile("cp.async.wait_group %0;" :: "n"(N) : "memory");
}

__device__ __forceinline__ void mma8(float* d, const uint32_t* a, const uint32_t* b) {
    asm volatile(
        "mma.sync.aligned.m16n8k8.row.col.f32.tf32.tf32.f32 "
        "{%0,%1,%2,%3}, {%4,%5,%6,%7}, {%8,%9}, {%0,%1,%2,%3};"
        : "+f"(d[0]), "+f"(d[1]), "+f"(d[2]), "+f"(d[3])
        : "r"(a[0]), "r"(a[1]), "r"(a[2]), "r"(a[3]), "r"(b[0]), "r"(b[1]));
}

// ---- fragment loaders (g = lane>>2, c = lane&3); raw fp32 in smem, cvt here ----
__device__ __forceinline__ void fragA_Kc(const float* T, int st, int m0, int k0, int g, int c, uint32_t* a) {
    const float* p = T + (m0 + g) * st + k0 + c;
    a[0] = f2tf(p[0]);  a[2] = f2tf(p[4]);
    p += 8 * st;
    a[1] = f2tf(p[0]);  a[3] = f2tf(p[4]);
}
__device__ __forceinline__ void fragB_Kc(const float* T, int st, int n0, int k0, int g, int c, uint32_t* b) {
    const float* p = T + (n0 + g) * st + k0 + c;
    b[0] = f2tf(p[0]);  b[1] = f2tf(p[4]);
}
__device__ __forceinline__ void fragB_Tc(const float* T, int n0, int k0, int g, int c, uint32_t* b) {
    const float* p = T + (k0 + c) * STT + n0 + g;
    b[0] = f2tf(p[0]);  b[1] = f2tf(p[4 * STT]);
}
// transposed A with per-k scale folded in (kdv: v * kdec[s])
__device__ __forceinline__ void fragA_Tsc(const float* T, int m0, int k0, int g, int c,
                                          float kd0, float kd1, uint32_t* a) {
    const float* p = T + (k0 + c) * STT + m0 + g;
    a[0] = f2tf(p[0] * kd0);  a[1] = f2tf(p[8] * kd0);
    p += 4 * STT;
    a[2] = f2tf(p[0] * kd1);  a[3] = f2tf(p[8] * kd1);
}
// already-tf32 smem (scores): plain loads
__device__ __forceinline__ void fragA_K(const float* T, int st, int m0, int k0, int g, int c, uint32_t* a) {
    const float* p = T + (m0 + g) * st + k0 + c;
    a[0] = __float_as_uint(p[0]);  a[2] = __float_as_uint(p[4]);
    p += 8 * st;
    a[1] = __float_as_uint(p[0]);  a[3] = __float_as_uint(p[4]);
}

// ---- cp.async chunk loaders (256 threads) ----
// A-chunk: 64 rows x 32 cols, rows [tb, tb+64), cols [dc*32, +32)
__device__ __forceinline__ void cp_a(const float* __restrict__ base, int tb, int dc, uint32_t d) {
    #pragma unroll
    for (int it = 0; it < 2; it++) {
        int i = threadIdx.x + it * THREADS;
        int r = i >> 3, c4 = (i & 7) << 2;
        cpa16(d + (uint32_t)(r * STK + c4) * 4, base + (tb + r) * 128 + dc * 32 + c4);
    }
}
// B-chunk: 128 rows x 32 cols
__device__ __forceinline__ void cp_b(const float* __restrict__ base, int dc, uint32_t d) {
    #pragma unroll
    for (int it = 0; it < 4; it++) {
        int i = threadIdx.x + it * THREADS;
        int r = i >> 3, c4 = (i & 7) << 2;
        cpa16(d + (uint32_t)(r * STK + c4) * 4, base + r * 128 + dc * 32 + c4);
    }
}
// T-chunk: 32 rows x 128 cols, rows [sc*32, +32)
__device__ __forceinline__ void cp_t(const float* __restrict__ base, int sc, uint32_t d) {
    #pragma unroll
    for (int it = 0; it < 4; it++) {
        int i = threadIdx.x + it * THREADS;
        int r = i >> 5, c4 = (i & 31) << 2;
        cpa16(d + (uint32_t)(r * STT + c4) * 4, base + (sc * 32 + r) * 128 + c4);
    }
}

// ---------------------------------------------------------------------------
// Kernel 1: g_states[bhc][e][d] = sum_s v[s][e] * k[s][d] * exp(-sl*(CHK-s))
// cp.async double-buffered s-chunks; kdec folded into v fragments.
// ---------------------------------------------------------------------------
__global__ void __launch_bounds__(THREADS, 2)
kdv_kernel(const float* __restrict__ k_g, const float* __restrict__ v_g,
           const float* __restrict__ s_g)
{
    extern __shared__ float sm[];
    const uint32_t smb = smem_u32(sm);
    float* tab = sm + KF_TAB;

    const int tid = threadIdx.x;
    const int bhc = blockIdx.x;
    const int bh = bhc >> 5, h = bh & (H_ - 1);
    const float sl = s_g[h];
    const size_t cbase = ((size_t)bh * N_ + (size_t)(bhc & 31) * CHK) * D_;

    if (tid < 128) tab[tid] = expf(-sl * (float)(CHK - tid));

    const float* kp = k_g + cbase;
    const float* vp = v_g + cbase;
    const uint32_t V[2] = { smb + KF_V0 * 4, smb + KF_V1 * 4 };
    const uint32_t K[2] = { smb + KF_K0 * 4, smb + KF_K1 * 4 };
    const float*   Vf[2] = { sm + KF_V0, sm + KF_V1 };
    const float*   Kf[2] = { sm + KF_K0, sm + KF_K1 };

    cp_t(vp, 0, V[0]);
    cp_t(kp, 0, K[0]);
    CP_COMMIT();

    const int lane = tid & 31, wid = tid >> 5;
    const int g = lane >> 2, c = lane & 3;
    const int m0w = (wid & 3) * 32, n0w = (wid >> 2) * 64;

    float acc[2][8][4];
    #pragma unroll
    for (int mt = 0; mt < 2; mt++)
        #pragma unroll
        for (int nt = 0; nt < 8; nt++)
            #pragma unroll
            for (int r = 0; r < 4; r++) acc[mt][nt][r] = 0.f;

    #pragma unroll 1
    for (int sc = 0; sc < 4; sc++) {
        if (sc < 3) {
            cp_t(vp, sc + 1, V[(sc + 1) & 1]);
            cp_t(kp, sc + 1, K[(sc + 1) & 1]);
            CP_COMMIT();
            cp_wait<1>();
        } else {
            cp_wait<0>();
        }
        __syncthreads();
        const float* A = Vf[sc & 1];
        const float* B = Kf[sc & 1];
        const int sbase = sc * 32;
        #pragma unroll
        for (int ks = 0; ks < 4; ks++) {
            const int k0 = ks * 8;
            const float kd0 = tab[sbase + k0 + c];
            const float kd1 = tab[sbase + k0 + c + 4];
            uint32_t af[2][4];
            fragA_Tsc(A, m0w,      k0, g, c, kd0, kd1, af[0]);
            fragA_Tsc(A, m0w + 16, k0, g, c, kd0, kd1, af[1]);
            #pragma unroll
            for (int nt = 0; nt < 8; nt++) {
                uint32_t bf[2];
                fragB_Tc(B, n0w + nt * 8, k0, g, c, bf);
                mma8(acc[0][nt], af[0], bf);
                mma8(acc[1][nt], af[1], bf);
            }
        }
        __syncthreads();
    }

    float* outp = g_states + (size_t)bhc * D_ * D_;
    #pragma unroll
    for (int mt = 0; mt < 2; mt++) {
        int r0 = m0w + mt * 16 + g;
        #pragma unroll
        for (int nt = 0; nt < 8; nt++) {
            int col = n0w + nt * 8 + 2 * c;
            *reinterpret_cast<float2*>(outp + r0 * 128 + col) =
                make_float2(acc[mt][nt][0], acc[mt][nt][1]);
            *reinterpret_cast<float2*>(outp + (r0 + 8) * 128 + col) =
                make_float2(acc[mt][nt][2], acc[mt][nt][3]);
        }
    }
}

// ---------------------------------------------------------------------------
// Kernel 2: exclusive decay scan over chunks (elementwise on [e][d] states)
// ---------------------------------------------------------------------------
__global__ void __launch_bounds__(THREADS, 1)
scan_kernel(const float* __restrict__ s_g)
{
    const int bh  = blockIdx.x >> 3;
    const int sli = blockIdx.x & 7;
    const int h   = bh & (H_ - 1);
    const float bd = expf(-s_g[h] * (float)CHK);
    const int tid = threadIdx.x;

    int u0 = tid,       d0 = u0 >> 2, q0 = u0 & 3;
    int u1 = tid + 256, d1 = u1 >> 2, q1 = u1 & 3;
    const int off0 = d0 * 32 + sli * 4 + q0;
    const int off1 = d1 * 32 + sli * 4 + q1;

    float4* base = reinterpret_cast<float4*>(g_states) + (size_t)bh * NBLK * (D_ * D_ / 4);
    float4 r0 = make_float4(0.f, 0.f, 0.f, 0.f), r1 = r0;
    for (int cc = 0; cc < NBLK; cc++) {
        float4* p = base + (size_t)cc * (D_ * D_ / 4);
        float4 t0 = p[off0], t1 = p[off1];
        p[off0] = r0;  p[off1] = r1;
        r0.x = bd * r0.x + t0.x;  r0.y = bd * r0.y + t0.y;
        r0.z = bd * r0.z + t0.z;  r0.w = bd * r0.w + t0.w;
        r1.x = bd * r1.x + t1.x;  r1.y = bd * r1.y + t1.y;
        r1.z = bd * r1.z + t1.z;  r1.w = bd * r1.w + t1.w;
    }
}

// ---------------------------------------------------------------------------
// Kernel 3 (t-split, grid 2048): per (b,h,chunk,thalf), 64 t-rows:
//   GEMM1 (stream d): sc[t][s] = mask * exp(-sl(t-s)) * (q . k)
//   GEMM2 (stream d): inter = q @ S; scale rows by exp(-sl t)
//   GEMM3 (stream s): o = inter + sc @ v
// ---------------------------------------------------------------------------
__global__ void __launch_bounds__(THREADS, 2)
out_kernel(const float* __restrict__ q_g, const float* __restrict__ k_g,
           const float* __restrict__ v_g, const float* __restrict__ s_g,
           float* __restrict__ o_g)
{
    extern __shared__ float sm[];
    const uint32_t smb = smem_u32(sm);
    float* tab  = sm + OF_TAB;
    float* bufS = sm + OF_SC;

    const int tid = threadIdx.x;
    const int bhc = blockIdx.x >> 1;
    const int tb  = (blockIdx.x & 1) * 64;
    const int bh = bhc >> 5, h = bh & (H_ - 1);
    const float sl = s_g[h];
    const size_t cbase = ((size_t)bh * N_ + (size_t)(bhc & 31) * CHK) * D_;

    if (tid < 128) tab[tid] = expf(-sl * (float)tid);

    const float* qp = q_g + cbase;
    const float* kp = k_g + cbase;
    const float* vp = v_g + cbase;
    const float* Sp = g_states + (size_t)bhc * D_ * D_;

    const uint32_t A[2] = { smb + OF_A0 * 4, smb + OF_A1 * 4 };
    const uint32_t B[2] = { smb + OF_B0 * 4, smb + OF_B1 * 4 };
    const float*   Af[2] = { sm + OF_A0, sm + OF_A1 };
    const float*   Bf[2] = { sm + OF_B0, sm + OF_B1 };

    const int lane = tid & 31, wid = tid >> 5;
    const int g = lane >> 2, c = lane & 3;
    const int m0w = (wid & 1) * 32, n0w = (wid >> 1) * 32;

    float acc[2][4][4];
    #pragma unroll
    for (int mt = 0; mt < 2; mt++)
        #pragma unroll
        for (int nt = 0; nt < 4; nt++)
            #pragma unroll
            for (int r = 0; r < 4; r++) acc[mt][nt][r] = 0.f;

    // ---- GEMM1: scores = q . k^T (stream d-chunks) ----
    cp_a(qp, tb, 0, A[0]);
    cp_b(kp, 0, B[0]);
    CP_COMMIT();
    #pragma unroll 1
    for (int dc = 0; dc < 4; dc++) {
        if (dc < 3) {
            cp_a(qp, tb, dc + 1, A[(dc + 1) & 1]);
            cp_b(kp, dc + 1, B[(dc + 1) & 1]);
            CP_COMMIT();
            cp_wait<1>();
        } else {
            cp_wait<0>();
        }
        __syncthreads();
        const float* Aq = Af[dc & 1];
        const float* Bk = Bf[dc & 1];
        #pragma unroll
        for (int ks = 0; ks < 4; ks++) {
            const int k0 = ks * 8;
            uint32_t af[2][4];
            fragA_Kc(Aq, STK, m0w,      k0, g, c, af[0]);
            fragA_Kc(Aq, STK, m0w + 16, k0, g, c, af[1]);
            #pragma unroll
            for (int nt = 0; nt < 4; nt++) {
                uint32_t bf[2];
                fragB_Kc(Bk, STK, n0w + nt * 8, k0, g, c, bf);
                mma8(acc[0][nt], af[0], bf);
                mma8(acc[1][nt], af[1], bf);
            }
        }
        __syncthreads();
    }

    // ---- transform -> bufS (mask + decay + tf32), zero acc ----
    #pragma unroll
    for (int mt = 0; mt < 2; mt++) {
        int lt0 = m0w + mt * 16 + g, lt1 = lt0 + 8;
        int t0 = tb + lt0, t1 = tb + lt1;
        #pragma unroll
        for (int nt = 0; nt < 4; nt++) {
            int s0 = n0w + nt * 8 + 2 * c;
            float w00 = (t0 >= s0)     ? acc[mt][nt][0] * tab[t0 - s0]     : 0.f;
            float w01 = (t0 >= s0 + 1) ? acc[mt][nt][1] * tab[t0 - s0 - 1] : 0.f;
            float w10 = (t1 >= s0)     ? acc[mt][nt][2] * tab[t1 - s0]     : 0.f;
            float w11 = (t1 >= s0 + 1) ? acc[mt][nt][3] * tab[t1 - s0 - 1] : 0.f;
            bufS[lt0 * STS_ + s0]     = __uint_as_float(f2tf(w00));
            bufS[lt0 * STS_ + s0 + 1] = __uint_as_float(f2tf(w01));
            bufS[lt1 * STS_ + s0]     = __uint_as_float(f2tf(w10));
            bufS[lt1 * STS_ + s0 + 1] = __uint_as_float(f2tf(w11));
            acc[mt][nt][0] = acc[mt][nt][1] = acc[mt][nt][2] = acc[mt][nt][3] = 0.f;
        }
    }

    // ---- GEMM2: inter = q @ S (stream d-chunks; S[e][d]: n=e, k=d) ----
    cp_a(qp, tb, 0, A[0]);
    cp_b(Sp, 0, B[0]);
    CP_COMMIT();
    #pragma unroll 1
    for (int dc = 0; dc < 4; dc++) {
        if (dc < 3) {
            cp_a(qp, tb, dc + 1, A[(dc + 1) & 1]);
            cp_b(Sp, dc + 1, B[(dc + 1) & 1]);
            CP_COMMIT();
            cp_wait<1>();
        } else {
            cp_wait<0>();
        }
        __syncthreads();
        const float* Aq = Af[dc & 1];
        const float* Bs = Bf[dc & 1];
        #pragma unroll
        for (int ks = 0; ks < 4; ks++) {
            const int k0 = ks * 8;
            uint32_t af[2][4];
            fragA_Kc(Aq, STK, m0w,      k0, g, c, af[0]);
            fragA_Kc(Aq, STK, m0w + 16, k0, g, c, af[1]);
            #pragma unroll
            for (int nt = 0; nt < 4; nt++) {
                uint32_t bf[2];
                fragB_Kc(Bs, STK, n0w + nt * 8, k0, g, c, bf);
                mma8(acc[0][nt], af[0], bf);
                mma8(acc[1][nt], af[1], bf);
            }
        }
        __syncthreads();
    }

    // scale inter rows by exp(-sl * t)
    #pragma unroll
    for (int mt = 0; mt < 2; mt++) {
        float f0 = tab[tb + m0w + mt * 16 + g];
        float f1 = tab[tb + m0w + mt * 16 + g + 8];
        #pragma unroll
        for (int nt = 0; nt < 4; nt++) {
            acc[mt][nt][0] *= f0;  acc[mt][nt][1] *= f0;
            acc[mt][nt][2] *= f1;  acc[mt][nt][3] *= f1;
        }
    }

    // ---- GEMM3: o += sc @ v (stream s-chunks; v [s][e] T-chunks in B bufs) ----
    cp_t(vp, 0, B[0]);
    CP_COMMIT();
    #pragma unroll 1
    for (int sc = 0; sc < 4; sc++) {
        if (sc < 3) {
            cp_t(vp, sc + 1, B[(sc + 1) & 1]);
            CP_COMMIT();
            cp_wait<1>();
        } else {
            cp_wait<0>();
        }
        __syncthreads();
        const float* Bv = Bf[sc & 1];
        const int kbase = sc * 32;
        #pragma unroll
        for (int ks = 0; ks < 4; ks++) {
            const int k0 = ks * 8;
            uint32_t af[2][4];
            fragA_K(bufS, STS_, m0w,      kbase + k0, g, c, af[0]);
            fragA_K(bufS, STS_, m0w + 16, kbase + k0, g, c, af[1]);
            #pragma unroll
            for (int nt = 0; nt < 4; nt++) {
                uint32_t bf[2];
                fragB_Tc(Bv, n0w + nt * 8, k0, g, c, bf);
                mma8(acc[0][nt], af[0], bf);
                mma8(acc[1][nt], af[1], bf);
            }
        }
        __syncthreads();
    }

    float* oc = o_g + cbase;
    #pragma unroll
    for (int mt = 0; mt < 2; mt++) {
        int r0 = tb + m0w + mt * 16 + g;
        #pragma unroll
        for (int nt = 0; nt < 4; nt++) {
            int col = n0w + nt * 8 + 2 * c;
            *reinterpret_cast<float2*>(oc + r0 * 128 + col) =
                make_float2(acc[mt][nt][0], acc[mt][nt][1]);
            *reinterpret_cast<float2*>(oc + (r0 + 8) * 128 + col) =
                make_float2(acc[mt][nt][2], acc[mt][nt][3]);
        }
    }
}

// ---------------------------------------------------------------------------
extern "C" void kernel_launch(void* const* d_in, const int* in_sizes, int n_in,
                              void* d_out, int out_size)
{
    const float* q = (const float*)d_in[0];
    const float* k = (const float*)d_in[1];
    const float* v = (const float*)d_in[2];
    const float* s = (const float*)d_in[3];
    float* o = (float*)d_out;

    cudaFuncSetAttribute(kdv_kernel, cudaFuncAttributeMaxDynamicSharedMemorySize, SMEM_KDV);
    cudaFuncSetAttribute(out_kernel, cudaFuncAttributeMaxDynamicSharedMemorySize, SMEM_OUT);

    kdv_kernel<<<NCTA, THREADS, SMEM_KDV>>>(k, v, s);
    scan_kernel<<<BHc * 8, THREADS>>>(s);
    out_kernel<<<NCTA * 2, THREADS, SMEM_OUT>>>(q, k, v, s, o);
}